// round 13
// baseline (speedup 1.0000x reference)
#include <cuda_runtime.h>
#include <cuda_bf16.h>
#include <math.h>

#define BATCH 2
#define SEQ   2048
#define DIM   1024
#define HEADS 16
#define HDIM  64
#define BH    (BATCH*HEADS)          // 32
#define MROWS (BATCH*SEQ)            // 4096
#define QKVN  (3*DIM)                // 3072

typedef unsigned short ushortT;
typedef unsigned int   u32;

// ---------------- scratch (device globals) -------------------------------------
__device__ float   g_o[BH * SEQ * HDIM];
__device__ float   g_bias3[QKVN];
__device__ ushortT g_xh[MROWS * DIM],  g_xl[MROWS * DIM];
__device__ ushortT g_wh[QKVN * DIM],   g_wl[QKVN * DIM];
__device__ ushortT g_pwh[DIM * DIM],   g_pwl[DIM * DIM];
__device__ ushortT g_qh[BH*SEQ*HDIM], g_ql[BH*SEQ*HDIM];
__device__ ushortT g_kh[BH*SEQ*HDIM], g_kl[BH*SEQ*HDIM];
__device__ ushortT g_vh[BH*SEQ*HDIM], g_vl[BH*SEQ*HDIM];
__device__ ushortT g_lnh[MROWS * DIM], g_lnl[MROWS * DIM];

// ---------------- helpers ------------------------------------------------------
__device__ __forceinline__ unsigned short b2u(__nv_bfloat16 x) {
    return *reinterpret_cast<unsigned short*>(&x);
}
__device__ __forceinline__ float u2f(unsigned short u) {
    __nv_bfloat16_raw r; r.x = u;
    __nv_bfloat16 b = r;
    return __bfloat162float(b);
}
__device__ __forceinline__ void split1(float x, unsigned short& h, unsigned short& l) {
    __nv_bfloat16 hb = __float2bfloat16_rn(x);
    float res = x - __bfloat162float(hb);
    __nv_bfloat16 lb = __float2bfloat16_rn(res);
    h = b2u(hb); l = b2u(lb);
}
__device__ __forceinline__ void splitpair(float x0, float x1, u32& h, u32& l) {
    unsigned short h0, l0, h1, l1;
    split1(x0, h0, l0); split1(x1, h1, l1);
    h = (u32)h0 | ((u32)h1 << 16);
    l = (u32)l0 | ((u32)l1 << 16);
}
__device__ __forceinline__ void mma16816(float* c, const u32* a, const u32* b) {
    asm volatile(
        "mma.sync.aligned.m16n8k16.row.col.f32.bf16.bf16.f32 "
        "{%0,%1,%2,%3}, {%4,%5,%6,%7}, {%8,%9}, {%0,%1,%2,%3};\n"
        : "+f"(c[0]), "+f"(c[1]), "+f"(c[2]), "+f"(c[3])
        : "r"(a[0]), "r"(a[1]), "r"(a[2]), "r"(a[3]), "r"(b[0]), "r"(b[1]));
}
__device__ __forceinline__ u32 smem_u32(const void* p) {
    return (u32)__cvta_generic_to_shared(p);
}
__device__ __forceinline__ void ldsm_x4(u32& r0, u32& r1, u32& r2, u32& r3, u32 addr) {
    asm volatile("ldmatrix.sync.aligned.m8n8.x4.shared.b16 {%0,%1,%2,%3}, [%4];"
                 : "=r"(r0), "=r"(r1), "=r"(r2), "=r"(r3) : "r"(addr));
}
__device__ __forceinline__ void ldsm_x4_trans(u32& r0, u32& r1, u32& r2, u32& r3, u32 addr) {
    asm volatile("ldmatrix.sync.aligned.m8n8.x4.trans.shared.b16 {%0,%1,%2,%3}, [%4];"
                 : "=r"(r0), "=r"(r1), "=r"(r2), "=r"(r3) : "r"(addr));
}
__device__ __forceinline__ void cpasync16(u32 saddr, const void* g) {
    asm volatile("cp.async.cg.shared.global [%0], [%1], 16;" :: "r"(saddr), "l"(g) : "memory");
}

// ---------------- fused prologue: all splits + merged bias ---------------------
#define XN (MROWS*DIM)           // 4194304
#define WN (QKVN*DIM)            // 3145728
#define PWN (DIM*DIM)            // 1048576
#define TOTSPLIT (XN + WN + PWN + QKVN)

__global__ void fused_split_kernel(const float* __restrict__ x,
                                   const float* __restrict__ qkv_w,
                                   const float* __restrict__ proj_w,
                                   const float* __restrict__ qb,
                                   const float* __restrict__ vb) {
    int i = blockIdx.x * 256 + threadIdx.x;
    if (i < XN) {
        unsigned short hh, ll; split1(x[i], hh, ll);
        g_xh[i] = hh; g_xl[i] = ll;
    } else if (i < XN + WN) {
        int j = i - XN;
        unsigned short hh, ll; split1(qkv_w[j], hh, ll);
        g_wh[j] = hh; g_wl[j] = ll;
    } else if (i < XN + WN + PWN) {
        int j = i - XN - WN;
        unsigned short hh, ll; split1(proj_w[j], hh, ll);
        g_pwh[j] = hh; g_pwl[j] = ll;
    } else if (i < TOTSPLIT) {
        int j = i - XN - WN - PWN;
        float v = 0.0f;
        if (j < DIM) v = qb[j];
        else if (j >= 2*DIM) v = vb[j - 2*DIM];
        g_bias3[j] = v;
    }
}

// ---------------- GEMM bf16x3, 128x128 CTA, 64x32 warp tile, ldmatrix ----------
#define BM 128
#define BN 128
#define BKS 32
#define STR 40
#define ARR_U (BM * STR)                 // 5120 ushorts per sub-array
#define STAGE_U (4 * ARR_U)              // 20480 ushorts per stage
#define GEMM_DSMEM (2 * STAGE_U * 2)     // 81920 bytes

__global__ __launch_bounds__(256, 2)
void gemm_bf16x3_v5(const ushortT* __restrict__ Ah, const ushortT* __restrict__ Al,
                    const ushortT* __restrict__ Bh, const ushortT* __restrict__ Bl,
                    const float* __restrict__ bias, float* __restrict__ C,
                    int M, int N, int K, int mode, const float* __restrict__ pe) {
    extern __shared__ ushortT S[];
    const int tid = threadIdx.x, lane = tid & 31, wid = tid >> 5;
    const int wm = wid >> 2, wn = wid & 3;       // 2 x 4 warp grid
    const int g = lane >> 2, t = lane & 3;
    const int m0 = blockIdx.y * BM, n0 = blockIdx.x * BN;

    const int a_row = lane & 15;
    const int a_ko  = (lane >> 4) * 8;
    const int b_row = ((lane >> 4) << 3) | (lane & 7);
    const int b_ko  = ((lane >> 3) & 1) * 8;

    float acc[4][4][4];
#pragma unroll
    for (int a = 0; a < 4; a++)
#pragma unroll
        for (int b = 0; b < 4; b++)
#pragma unroll
            for (int c = 0; c < 4; c++) acc[a][b][c] = 0.0f;

#define ISSUE(SG) {                                                           \
    ushortT* st = S + ((SG) & 1) * STAGE_U;                                   \
    const int k0 = (SG) * BKS;                                                \
    _Pragma("unroll")                                                         \
    for (int i = 0; i < 2; i++) {                                             \
        int sl = tid + i*256, row = sl >> 2, cg = sl & 3;                     \
        size_t ga = (size_t)(m0 + row) * K + k0 + cg*8;                       \
        size_t gb = (size_t)(n0 + row) * K + k0 + cg*8;                       \
        u32 so = (u32)(row*STR + cg*8);                                       \
        cpasync16(smem_u32(st) + so*2, Ah + ga);                              \
        cpasync16(smem_u32(st + ARR_U) + so*2, Al + ga);                      \
        cpasync16(smem_u32(st + 2*ARR_U) + so*2, Bh + gb);                    \
        cpasync16(smem_u32(st + 3*ARR_U) + so*2, Bl + gb);                    \
    }                                                                         \
    asm volatile("cp.async.commit_group;" ::: "memory");                      \
    }

    const int NS = K / BKS;
    ISSUE(0);
    for (int s = 0; s < NS; s++) {
        if (s + 1 < NS) {
            ISSUE(s + 1);
            asm volatile("cp.async.wait_group 1;" ::: "memory");
        } else {
            asm volatile("cp.async.wait_group 0;" ::: "memory");
        }
        __syncthreads();

        const ushortT* st = S + (s & 1) * STAGE_U;
        const ushortT* pAh = st;
        const ushortT* pAl = st + ARR_U;
        const ushortT* pBh = st + 2*ARR_U;
        const ushortT* pBl = st + 3*ARR_U;
#pragma unroll
        for (int kc = 0; kc < 2; kc++) {
            u32 bh_[4][2], bl_[4][2];
#pragma unroll
            for (int pr = 0; pr < 2; pr++) {
                int off = (wn*32 + pr*16 + b_row) * STR + kc*16 + b_ko;
                ldsm_x4(bh_[2*pr][0], bh_[2*pr][1], bh_[2*pr+1][0], bh_[2*pr+1][1],
                        smem_u32(pBh + off));
                ldsm_x4(bl_[2*pr][0], bl_[2*pr][1], bl_[2*pr+1][0], bl_[2*pr+1][1],
                        smem_u32(pBl + off));
            }
#pragma unroll
            for (int mt = 0; mt < 4; mt++) {
                int aoff = (wm*64 + mt*16 + a_row) * STR + kc*16 + a_ko;
                u32 ah[4], al[4];
                ldsm_x4(ah[0], ah[1], ah[2], ah[3], smem_u32(pAh + aoff));
                ldsm_x4(al[0], al[1], al[2], al[3], smem_u32(pAl + aoff));
#pragma unroll
                for (int nt = 0; nt < 4; nt++) mma16816(acc[mt][nt], ah, bh_[nt]);
#pragma unroll
                for (int nt = 0; nt < 4; nt++) mma16816(acc[mt][nt], ah, bl_[nt]);
#pragma unroll
                for (int nt = 0; nt < 4; nt++) mma16816(acc[mt][nt], al, bh_[nt]);
            }
        }
        __syncthreads();
    }
#undef ISSUE

    if (mode == 0) {
#pragma unroll
        for (int mt = 0; mt < 4; mt++) {
            int m = m0 + wm*64 + mt*16 + g;
#pragma unroll
            for (int nt = 0; nt < 4; nt++) {
                int c = n0 + wn*32 + nt*8 + 2*t;
                float b0 = bias[c], b1 = bias[c + 1];
                float2 v0 = make_float2(acc[mt][nt][0] + b0, acc[mt][nt][1] + b1);
                float2 v1 = make_float2(acc[mt][nt][2] + b0, acc[mt][nt][3] + b1);
                *(float2*)&C[(size_t)m * N + c] = v0;
                *(float2*)&C[(size_t)(m + 8) * N + c] = v1;
            }
        }
    } else {
#pragma unroll
        for (int mt = 0; mt < 4; mt++) {
#pragma unroll
            for (int nt = 0; nt < 4; nt++) {
                int c = n0 + wn*32 + nt*8 + 2*t;
                float b0 = bias[c], b1 = bias[c + 1];
                int sec = c >> 10;
                int h = (c & 1023) >> 6;
                int d2 = (c & 63) >> 1;
#pragma unroll
                for (int half = 0; half < 2; half++) {
                    int m = m0 + wm*64 + mt*16 + g + half*8;
                    int n = m & (SEQ - 1);
                    int b = m >> 11;
                    float v0 = acc[mt][nt][half*2]     + b0;
                    float v1 = acc[mt][nt][half*2 + 1] + b1;
                    float r0, r1;
                    ushortT *dh, *dl;
                    if (sec < 2) {
                        const float* p = &pe[((size_t)n * 32 + d2) * 4];
                        float p00 = p[0], p01 = p[1], p10 = p[2], p11 = p[3];
                        r0 = p00*v0 + p01*v1;
                        r1 = p10*v0 + p11*v1;
                        if (sec == 0) { r0 *= 0.125f; r1 *= 0.125f; dh = g_qh; dl = g_ql; }
                        else          { dh = g_kh; dl = g_kl; }
                    } else {
                        r0 = v0; r1 = v1; dh = g_vh; dl = g_vl;
                    }
                    size_t idx = (((size_t)(b * HEADS + h)) * SEQ + n) * 32 + d2;
                    u32 hh, ll;
                    splitpair(r0, r1, hh, ll);
                    ((u32*)dh)[idx] = hh;
                    ((u32*)dl)[idx] = ll;
                }
            }
        }
    }
}

// ---------------- k_mean -------------------------------------------------------
__global__ void kmean_kernel(float* __restrict__ out) {
    int idx = blockIdx.x * 256 + threadIdx.x;
    int d = idx & 63;
    int n = (idx >> 6) & 2047;
    int b = idx >> 17;
    float s = 0.0f;
#pragma unroll
    for (int h = 0; h < HEADS; h++) {
        size_t o = (((size_t)(b * HEADS + h)) * SEQ + n) * HDIM + d;
        s += u2f(g_kh[o]) + u2f(g_kl[o]);
    }
    out[idx] = s * (1.0f / 16.0f);
}

// ---------------- flash v2: cp.async double-buffer + hi-fragment reuse ---------
#define VSTR 72
#define FARR_U (64 * VSTR)               // 4608 ushorts per array
#define FSTAGE_U (4 * FARR_U)            // 18432 ushorts per stage
#define FLASH_DSMEM (2 * FSTAGE_U * 2)   // 73728 bytes

__global__ __launch_bounds__(256)
void flash_bf16x3_v2() {
    extern __shared__ ushortT FS[];
    const int tid = threadIdx.x, lane = tid & 31, wid = tid >> 5;
    const int g = lane >> 2, t = lane & 3;
    const int bh = blockIdx.y;
    const int q0 = blockIdx.x * 128;
    const size_t base = (size_t)bh * SEQ * HDIM;

    const int b_row = ((lane >> 4) << 3) | (lane & 7);
    const int b_ko  = ((lane >> 3) & 1) * 8;
    const int v_row = ((lane >> 3) & 1) * 8 + (lane & 7);
    const int v_col = (lane >> 4) * 8;

    u32 qfh[4][4], qfl[4][4];
    {
        int r0 = q0 + wid*16 + g;
        const ushortT* ph = g_qh + base + (size_t)r0 * HDIM;
        const ushortT* pl = g_ql + base + (size_t)r0 * HDIM;
#pragma unroll
        for (int c = 0; c < 4; c++) {
            int ko = c*16 + 2*t;
            qfh[c][0] = *(const u32*)(ph + ko);
            qfh[c][1] = *(const u32*)(ph + 8*HDIM + ko);
            qfh[c][2] = *(const u32*)(ph + ko + 8);
            qfh[c][3] = *(const u32*)(ph + 8*HDIM + ko + 8);
            qfl[c][0] = *(const u32*)(pl + ko);
            qfl[c][1] = *(const u32*)(pl + 8*HDIM + ko);
            qfl[c][2] = *(const u32*)(pl + ko + 8);
            qfl[c][3] = *(const u32*)(pl + 8*HDIM + ko + 8);
        }
    }

    float o[8][4];
#pragma unroll
    for (int a = 0; a < 8; a++)
#pragma unroll
        for (int b = 0; b < 4; b++) o[a][b] = 0.0f;
    float mi0 = -1e30f, mi1 = -1e30f, li0 = 0.0f, li1 = 0.0f;

    // cp.async K/V tile loader: 64 rows x 128B per array, 4 arrays
#define FISSUE(IT) {                                                          \
    ushortT* st = FS + ((IT) & 1) * FSTAGE_U;                                 \
    const int n0_ = (IT) * 64;                                                \
    _Pragma("unroll")                                                         \
    for (int i = 0; i < 2; i++) {                                             \
        int sl = tid + i*256, row = sl >> 3, cg = sl & 7;                     \
        size_t off = base + (size_t)(n0_ + row) * HDIM + cg*8;                \
        u32 so = (u32)(row*VSTR + cg*8) * 2;                                  \
        cpasync16(smem_u32(st) + so, g_kh + off);                             \
        cpasync16(smem_u32(st + FARR_U) + so, g_kl + off);                    \
        cpasync16(smem_u32(st + 2*FARR_U) + so, g_vh + off);                  \
        cpasync16(smem_u32(st + 3*FARR_U) + so, g_vl + off);                  \
    }                                                                         \
    asm volatile("cp.async.commit_group;" ::: "memory");                      \
    }

    const int NS = SEQ / 64;
    FISSUE(0);
    for (int it = 0; it < NS; it++) {
        if (it + 1 < NS) {
            FISSUE(it + 1);
            asm volatile("cp.async.wait_group 1;" ::: "memory");
        } else {
            asm volatile("cp.async.wait_group 0;" ::: "memory");
        }
        __syncthreads();

        const ushortT* st = FS + (it & 1) * FSTAGE_U;
        const ushortT* pKh = st;
        const ushortT* pKl = st + FARR_U;
        const ushortT* pVh = st + 2*FARR_U;
        const ushortT* pVl = st + 3*FARR_U;

        float sc[8][4];
#pragma unroll
        for (int a = 0; a < 8; a++)
#pragma unroll
            for (int b = 0; b < 4; b++) sc[a][b] = 0.0f;

        // S = Q K^T : load Kh/Kl fragments once per c, reuse Kh in pass 3
#pragma unroll
        for (int c = 0; c < 4; c++) {
            const int kbase = c*16 + b_ko;
            u32 kb_h[8][2], kb_l[8][2];
#pragma unroll
            for (int pr = 0; pr < 4; pr++)
                ldsm_x4(kb_h[2*pr][0], kb_h[2*pr][1], kb_h[2*pr+1][0], kb_h[2*pr+1][1],
                        smem_u32(&pKh[(pr*16 + b_row)*VSTR + kbase]));
#pragma unroll
            for (int pr = 0; pr < 4; pr++)
                ldsm_x4(kb_l[2*pr][0], kb_l[2*pr][1], kb_l[2*pr+1][0], kb_l[2*pr+1][1],
                        smem_u32(&pKl[(pr*16 + b_row)*VSTR + kbase]));
#pragma unroll
            for (int nt = 0; nt < 8; nt++) mma16816(sc[nt], qfh[c], kb_h[nt]);
#pragma unroll
            for (int nt = 0; nt < 8; nt++) mma16816(sc[nt], qfh[c], kb_l[nt]);
#pragma unroll
            for (int nt = 0; nt < 8; nt++) mma16816(sc[nt], qfl[c], kb_h[nt]);
        }

        float rm0 = -1e30f, rm1 = -1e30f;
#pragma unroll
        for (int nt = 0; nt < 8; nt++) {
            rm0 = fmaxf(rm0, fmaxf(sc[nt][0], sc[nt][1]));
            rm1 = fmaxf(rm1, fmaxf(sc[nt][2], sc[nt][3]));
        }
        rm0 = fmaxf(rm0, __shfl_xor_sync(0xffffffffu, rm0, 1));
        rm0 = fmaxf(rm0, __shfl_xor_sync(0xffffffffu, rm0, 2));
        rm1 = fmaxf(rm1, __shfl_xor_sync(0xffffffffu, rm1, 1));
        rm1 = fmaxf(rm1, __shfl_xor_sync(0xffffffffu, rm1, 2));
        float mn0 = fmaxf(mi0, rm0), mn1 = fmaxf(mi1, rm1);
        float a0 = __expf(mi0 - mn0), a1 = __expf(mi1 - mn1);
        float s0 = 0.0f, s1 = 0.0f;
#pragma unroll
        for (int nt = 0; nt < 8; nt++) {
            sc[nt][0] = __expf(sc[nt][0] - mn0); s0 += sc[nt][0];
            sc[nt][1] = __expf(sc[nt][1] - mn0); s0 += sc[nt][1];
            sc[nt][2] = __expf(sc[nt][2] - mn1); s1 += sc[nt][2];
            sc[nt][3] = __expf(sc[nt][3] - mn1); s1 += sc[nt][3];
        }
        s0 += __shfl_xor_sync(0xffffffffu, s0, 1);
        s0 += __shfl_xor_sync(0xffffffffu, s0, 2);
        s1 += __shfl_xor_sync(0xffffffffu, s1, 1);
        s1 += __shfl_xor_sync(0xffffffffu, s1, 2);
        li0 = li0 * a0 + s0; li1 = li1 * a1 + s1;
        mi0 = mn0; mi1 = mn1;
#pragma unroll
        for (int nt = 0; nt < 8; nt++) {
            o[nt][0] *= a0; o[nt][1] *= a0; o[nt][2] *= a1; o[nt][3] *= a1;
        }

        // O += P V : trans-ldmatrix, Vh fragments loaded once per j, reused
#pragma unroll
        for (int j = 0; j < 4; j++) {
            u32 ph[4], pl[4];
            splitpair(sc[2*j][0],   sc[2*j][1],   ph[0], pl[0]);
            splitpair(sc[2*j][2],   sc[2*j][3],   ph[1], pl[1]);
            splitpair(sc[2*j+1][0], sc[2*j+1][1], ph[2], pl[2]);
            splitpair(sc[2*j+1][2], sc[2*j+1][3], ph[3], pl[3]);
            const int krow = j*16 + v_row;
            u32 vb_h[8][2], vb_l[8][2];
#pragma unroll
            for (int pr = 0; pr < 4; pr++)
                ldsm_x4_trans(vb_h[2*pr][0], vb_h[2*pr][1], vb_h[2*pr+1][0], vb_h[2*pr+1][1],
                              smem_u32(&pVh[krow*VSTR + pr*16 + v_col]));
#pragma unroll
            for (int pr = 0; pr < 4; pr++)
                ldsm_x4_trans(vb_l[2*pr][0], vb_l[2*pr][1], vb_l[2*pr+1][0], vb_l[2*pr+1][1],
                              smem_u32(&pVl[krow*VSTR + pr*16 + v_col]));
#pragma unroll
            for (int nt = 0; nt < 8; nt++) mma16816(o[nt], ph, vb_h[nt]);
#pragma unroll
            for (int nt = 0; nt < 8; nt++) mma16816(o[nt], ph, vb_l[nt]);
#pragma unroll
            for (int nt = 0; nt < 8; nt++) mma16816(o[nt], pl, vb_h[nt]);
        }
        __syncthreads();
    }
#undef FISSUE

    float i0 = 1.0f / li0, i1 = 1.0f / li1;
    int r0 = q0 + wid*16 + g;
#pragma unroll
    for (int nt = 0; nt < 8; nt++) {
        int col = nt*8 + 2*t;
        float2 v0 = make_float2(o[nt][0]*i0, o[nt][1]*i0);
        float2 v1 = make_float2(o[nt][2]*i1, o[nt][3]*i1);
        *(float2*)&g_o[base + (size_t)r0 * HDIM + col] = v0;
        *(float2*)&g_o[base + (size_t)(r0+8) * HDIM + col] = v1;
    }
}

// ---------------- LayerNorm (gather heads, write bf16 hi/lo) -------------------
__global__ __launch_bounds__(256)
void ln_kernel(const float* __restrict__ gamma, const float* __restrict__ beta) {
    int bn = blockIdx.x;
    int b = bn >> 11;
    int n = bn & 2047;

    float vals[4];
    float s = 0.0f, ss = 0.0f;
#pragma unroll
    for (int ti = 0; ti < 4; ti++) {
        int c = threadIdx.x + ti * 256;
        int h = c >> 6, d = c & 63;
        float v = g_o[(((size_t)(b * HEADS + h)) * SEQ + n) * HDIM + d];
        vals[ti] = v; s += v; ss += v * v;
    }
#pragma unroll
    for (int m = 16; m; m >>= 1) {
        s  += __shfl_xor_sync(0xffffffffu, s, m);
        ss += __shfl_xor_sync(0xffffffffu, ss, m);
    }
    __shared__ float rs[8], rss[8];
    int w = threadIdx.x >> 5, lanei = threadIdx.x & 31;
    if (lanei == 0) { rs[w] = s; rss[w] = ss; }
    __syncthreads();
    float st = 0.0f, sst = 0.0f;
#pragma unroll
    for (int i = 0; i < 8; i++) { st += rs[i]; sst += rss[i]; }

    float mean = st * (1.0f / 1024.0f);
    float var  = sst * (1.0f / 1024.0f) - mean * mean;
    float r = rsqrtf(var + 1e-5f);
#pragma unroll
    for (int ti = 0; ti < 4; ti++) {
        int c = threadIdx.x + ti * 256;
        float f = (vals[ti] - mean) * r * gamma[c] + beta[c];
        unsigned short hh, ll; split1(f, hh, ll);
        g_lnh[(size_t)bn * DIM + c] = hh;
        g_lnl[(size_t)bn * DIM + c] = ll;
    }
}

// ---------------- launch --------------------------------------------------------
extern "C" void kernel_launch(void* const* d_in, const int* in_sizes, int n_in,
                              void* d_out, int out_size) {
    const float* x      = (const float*)d_in[0];
    const float* pe     = (const float*)d_in[1];
    const float* qkv_w  = (const float*)d_in[2];
    const float* q_bias = (const float*)d_in[3];
    const float* v_bias = (const float*)d_in[4];
    const float* gamma  = (const float*)d_in[5];
    const float* beta   = (const float*)d_in[6];
    const float* proj_w = (const float*)d_in[7];
    const float* proj_b = (const float*)d_in[8];
    float* out = (float*)d_out;

    void *p_bias3;
    void *p_xh, *p_xl, *p_wh, *p_wl, *p_pwh, *p_pwl, *p_lnh, *p_lnl;
    cudaGetSymbolAddress(&p_bias3, g_bias3);
    cudaGetSymbolAddress(&p_xh, g_xh);   cudaGetSymbolAddress(&p_xl, g_xl);
    cudaGetSymbolAddress(&p_wh, g_wh);   cudaGetSymbolAddress(&p_wl, g_wl);
    cudaGetSymbolAddress(&p_pwh, g_pwh); cudaGetSymbolAddress(&p_pwl, g_pwl);
    cudaGetSymbolAddress(&p_lnh, g_lnh); cudaGetSymbolAddress(&p_lnl, g_lnl);

    cudaFuncSetAttribute(gemm_bf16x3_v5,
                         cudaFuncAttributeMaxDynamicSharedMemorySize, GEMM_DSMEM);
    cudaFuncSetAttribute(flash_bf16x3_v2,
                         cudaFuncAttributeMaxDynamicSharedMemorySize, FLASH_DSMEM);

    // 1) fused splits + bias
    fused_split_kernel<<<(TOTSPLIT + 255)/256, 256>>>(x, qkv_w, proj_w, q_bias, v_bias);

    // 2) QKV GEMM with fused bias + RoPE + hi/lo split epilogue
    gemm_bf16x3_v5<<<dim3(QKVN/BN, MROWS/BM), 256, GEMM_DSMEM>>>(
        (const ushortT*)p_xh, (const ushortT*)p_xl,
        (const ushortT*)p_wh, (const ushortT*)p_wl,
        (const float*)p_bias3, nullptr, MROWS, QKVN, DIM, 1, pe);

    // 3) k_mean
    kmean_kernel<<<(BATCH*SEQ*HDIM)/256, 256>>>(out + (size_t)MROWS * DIM);

    // 4) flash attention v2 (4th launch -> profiled)
    flash_bf16x3_v2<<<dim3(SEQ/128, BH), 256, FLASH_DSMEM>>>();

    // 5) layernorm
    ln_kernel<<<MROWS, 256>>>(gamma, beta);

    // 6) projection GEMM -> d_out
    gemm_bf16x3_v5<<<dim3(DIM/BN, MROWS/BM), 256, GEMM_DSMEM>>>(
        (const ushortT*)p_lnh, (const ushortT*)p_lnl,
        (const ushortT*)p_pwh, (const ushortT*)p_pwl,
        proj_b, out, MROWS, DIM, DIM, 0, nullptr);
}